// round 16
// baseline (speedup 1.0000x reference)
#include <cuda_runtime.h>
#include <cuda_bf16.h>
#include <stdint.h>

#define NB 32768   // batch rows
#define NK 1024    // codebook entries
#define ND 512     // feature dim
#define KBIG 1536  // 3-term split K: A=[hi|lo|hi], B=[hi|hi|lo]
#define EPSN 1e-8f

// ---------------- device scratch (no allocs allowed) ----------------
__device__ float g_sim[(size_t)NB * NK];   // 128 MB similarity scratch
__device__ float g_xinv[NB];
__device__ float g_cinv[NK];
__device__ __nv_bfloat16 g_ab[(size_t)NB * KBIG];  // 96 MB  [Ahi | Alo | Ahi]
__device__ __nv_bfloat16 g_bb[(size_t)NK * KBIG];  //  3 MB  [Bhi | Bhi | Blo]

// ---------------- PTX helpers (baseline ISA only: sm_80+) ----------------
__device__ __forceinline__ uint32_t smem_u32(const void* p) {
    uint32_t a;
    asm("{ .reg .u64 t; cvta.to.shared.u64 t, %1; cvt.u32.u64 %0, t; }" : "=r"(a) : "l"(p));
    return a;
}
#define CP_ASYNC16(saddr, gptr) \
    asm volatile("cp.async.cg.shared.global [%0], [%1], 16;" :: "r"(saddr), "l"(gptr) : "memory")
#define CP_COMMIT() asm volatile("cp.async.commit_group;" ::: "memory")
#define LDSM_X4(r0, r1, r2, r3, addr) \
    asm volatile("ldmatrix.sync.aligned.m8n8.x4.shared.b16 {%0,%1,%2,%3}, [%4];" \
        : "=r"(r0), "=r"(r1), "=r"(r2), "=r"(r3) : "r"(addr))
#define MMA16816(D, A, B) \
    asm volatile("mma.sync.aligned.m16n8k16.row.col.f32.bf16.bf16.f32 " \
        "{%0,%1,%2,%3}, {%4,%5,%6,%7}, {%8,%9}, {%0,%1,%2,%3};" \
        : "+f"((D)[0]), "+f"((D)[1]), "+f"((D)[2]), "+f"((D)[3]) \
        : "r"((A)[0]), "r"((A)[1]), "r"((A)[2]), "r"((A)[3]), "r"((B)[0]), "r"((B)[1]))

// integer add forced onto the fma pipe: IMAD d = a*one + b (one==1 at runtime)
__device__ __forceinline__ uint32_t addi(uint32_t a, uint32_t one, uint32_t b) {
    uint32_t d;
    asm("mad.lo.u32 %0, %1, %2, %3;" : "=r"(d) : "r"(a), "r"(one), "r"(b));
    return d;
}

// ---------------- threefry2x32, adds on fma pipe (bit-identical) ----------------
__device__ __forceinline__ uint2 tf2x32_imad(uint32_t k0, uint32_t k1,
                                             uint32_t x0, uint32_t x1, uint32_t one) {
    uint32_t k2 = k0 ^ k1 ^ 0x1BD11BDAu;
    x0 = addi(x0, one, k0); x1 = addi(x1, one, k1);
#define TF_ROT(r) { x0 = addi(x0, one, x1); x1 = __funnelshift_l(x1, x1, r); x1 ^= x0; }
    TF_ROT(13) TF_ROT(15) TF_ROT(26) TF_ROT(6)
    x0 = addi(x0, one, k1); x1 = addi(x1, one, k2 + 1u);
    TF_ROT(17) TF_ROT(29) TF_ROT(16) TF_ROT(24)
    x0 = addi(x0, one, k2); x1 = addi(x1, one, k0 + 2u);
    TF_ROT(13) TF_ROT(15) TF_ROT(26) TF_ROT(6)
    x0 = addi(x0, one, k0); x1 = addi(x1, one, k1 + 3u);
    TF_ROT(17) TF_ROT(29) TF_ROT(16) TF_ROT(24)
    x0 = addi(x0, one, k1); x1 = addi(x1, one, k2 + 4u);
    TF_ROT(13) TF_ROT(15) TF_ROT(26) TF_ROT(6)
    x0 = addi(x0, one, k2); x1 = addi(x1, one, k0 + 5u);
#undef TF_ROT
    return make_uint2(x0, x1);
}
__device__ __forceinline__ uint32_t rbits32(uint32_t k0, uint32_t k1,
                                            uint32_t flat, uint32_t one) {
    uint2 r = tf2x32_imad(k0, k1, 0u, flat, one);
    return r.x ^ r.y;
}
__device__ __forceinline__ float uniform_bits(uint32_t bits) {
    float f = __uint_as_float((bits >> 9) | 0x3f800000u) - 1.0f;
    return fmaxf(f + 1e-20f, 1e-20f);
}

// ---------------- fused prep: inv-norm + 3-term bf16 split (one read) ----------------
__global__ __launch_bounds__(128) void prep_kernel(const float* __restrict__ src, int which) {
    const int row = blockIdx.x;
    const int t = threadIdx.x;
    const float4 v = ((const float4*)(src + (size_t)row * ND))[t];

    float s = v.x * v.x + v.y * v.y + v.z * v.z + v.w * v.w;
#pragma unroll
    for (int o = 16; o; o >>= 1) s += __shfl_xor_sync(0xffffffffu, s, o);
    __shared__ float sm[4];
    if ((t & 31) == 0) sm[t >> 5] = s;
    __syncthreads();
    if (t == 0) {
        float tot = sm[0] + sm[1] + sm[2] + sm[3];
        float inv = 1.0f / fmaxf(sqrtf(tot), EPSN);
        if (which == 0) g_xinv[row] = inv; else g_cinv[row] = inv;
    }

    __nv_bfloat16 h0 = __float2bfloat16_rn(v.x), h1 = __float2bfloat16_rn(v.y);
    __nv_bfloat16 h2 = __float2bfloat16_rn(v.z), h3 = __float2bfloat16_rn(v.w);
    __nv_bfloat16 l0 = __float2bfloat16_rn(v.x - __bfloat162float(h0));
    __nv_bfloat16 l1 = __float2bfloat16_rn(v.y - __bfloat162float(h1));
    __nv_bfloat16 l2 = __float2bfloat16_rn(v.z - __bfloat162float(h2));
    __nv_bfloat16 l3 = __float2bfloat16_rn(v.w - __bfloat162float(h3));
    __nv_bfloat162 hA(h0, h1), hB(h2, h3), lA(l0, l1), lB(l2, l3);
    __nv_bfloat16* dst = which ? g_bb : g_ab;
    __nv_bfloat16* base = dst + (size_t)row * KBIG + t * 4;
    __nv_bfloat162* s0 = (__nv_bfloat162*)(base);
    __nv_bfloat162* s1 = (__nv_bfloat162*)(base + ND);
    __nv_bfloat162* s2 = (__nv_bfloat162*)(base + 2 * ND);
    s0[0] = hA; s0[1] = hB;
    if (which == 0) { s1[0] = lA; s1[1] = lB; s2[0] = hA; s2[1] = hB; }
    else            { s1[0] = hA; s1[1] = hB; s2[0] = lA; s2[1] = lB; }
}

// ------- bf16 mma.sync GEMM: BM128 x BN256, warp tile 64x64, 3-stage, 1 blk/SM -------
#define BM 128
#define BN 256
#define BK 32
#define SSTR 40                           // smem row stride in bf16 (32 + 8 pad)
#define SA_BYTES (BM * SSTR * 2)          // 10240
#define SB_BYTES (BN * SSTR * 2)          // 20480
#define STAGE_TOT (SA_BYTES + SB_BYTES)   // 30720
#define SMEM_GEMM (3 * STAGE_TOT)         // 92160
#define NKT (KBIG / BK)                   // 48

__global__ void __maxnreg__(224) gemm_mma_kernel() {
    extern __shared__ __align__(16) char dynsm[];
    const int tid = threadIdx.x;
    const int wid = tid >> 5, l = tid & 31;
    const int wm = wid >> 2, wn = wid & 3;           // warp grid 2(m) x 4(n), tile 64x64
    const int bm = blockIdx.y * BM, bn = blockIdx.x * BN;

    uint32_t sA[3], sB[3];
#pragma unroll
    for (int s = 0; s < 3; s++) {
        sA[s] = smem_u32(dynsm + s * STAGE_TOT);
        sB[s] = smem_u32(dynsm + s * STAGE_TOT + SA_BYTES);
    }

    float d[4][8][4];
#pragma unroll
    for (int mi = 0; mi < 4; mi++)
#pragma unroll
        for (int ni = 0; ni < 8; ni++)
#pragma unroll
            for (int r = 0; r < 4; r++) d[mi][ni][r] = 0.0f;

    // per tile: A = 512 segs of 16B (128 rows x 4), B = 1024 segs (256 rows x 4)
#define LOAD_TILE(kt, buf) do { \
    int _k0 = (kt) * BK; \
    { int _s = tid;        int _r = _s >> 2, _c = _s & 3; \
      CP_ASYNC16(sA[buf] + _r * (SSTR * 2) + _c * 16, \
                 g_ab + (size_t)(bm + _r) * KBIG + _k0 + _c * 8); } \
    { int _s = tid + 256;  int _r = _s >> 2, _c = _s & 3; \
      CP_ASYNC16(sA[buf] + _r * (SSTR * 2) + _c * 16, \
                 g_ab + (size_t)(bm + _r) * KBIG + _k0 + _c * 8); } \
    _Pragma("unroll") \
    for (int _q = 0; _q < 4; _q++) { \
      int _s = tid + _q * 256; int _r = _s >> 2, _c = _s & 3; \
      CP_ASYNC16(sB[buf] + _r * (SSTR * 2) + _c * 16, \
                 g_bb + (size_t)(bn + _r) * KBIG + _k0 + _c * 8); } \
    CP_COMMIT(); \
} while (0)

    LOAD_TILE(0, 0);
    LOAD_TILE(1, 1);

    int buf = 0, nbuf = 2;
    for (int kt = 0; kt < NKT; kt++) {
        asm volatile("cp.async.wait_group 1;" ::: "memory");
        __syncthreads();
        if (kt + 2 < NKT) LOAD_TILE(kt + 2, nbuf);

#pragma unroll
        for (int ks = 0; ks < 2; ks++) {
            uint32_t a[4][4];
#pragma unroll
            for (int mi = 0; mi < 4; mi++) {
                int row = wm * 64 + mi * 16 + (l & 15);
                int col = ks * 16 + (l >> 4) * 8;
                LDSM_X4(a[mi][0], a[mi][1], a[mi][2], a[mi][3],
                        sA[buf] + row * (SSTR * 2) + col * 2);
            }
            uint32_t b[8][2];
#pragma unroll
            for (int p = 0; p < 4; p++) {
                int row = wn * 64 + p * 16 + (l & 7) + ((l >> 4) & 1) * 8;
                int col = ks * 16 + ((l >> 3) & 1) * 8;
                LDSM_X4(b[p * 2][0], b[p * 2][1], b[p * 2 + 1][0], b[p * 2 + 1][1],
                        sB[buf] + row * (SSTR * 2) + col * 2);
            }
#pragma unroll
            for (int mi = 0; mi < 4; mi++)
#pragma unroll
                for (int ni = 0; ni < 8; ni++)
                    MMA16816(d[mi][ni], a[mi], b[ni]);
        }
        buf = (buf == 2) ? 0 : buf + 1;
        nbuf = (nbuf == 2) ? 0 : nbuf + 1;
    }

    // epilogue: scale by inv norms, write fp32 sim
#pragma unroll
    for (int mi = 0; mi < 4; mi++) {
        int r0 = bm + wm * 64 + mi * 16 + (l >> 2);
        int r1 = r0 + 8;
        float xi0 = g_xinv[r0], xi1 = g_xinv[r1];
#pragma unroll
        for (int ni = 0; ni < 8; ni++) {
            int c0 = bn + wn * 64 + ni * 8 + ((l & 3) << 1);
            float cv0 = g_cinv[c0], cv1 = g_cinv[c0 + 1];
            *(float2*)(g_sim + (size_t)r0 * NK + c0) =
                make_float2(d[mi][ni][0] * xi0 * cv0, d[mi][ni][1] * xi0 * cv1);
            *(float2*)(g_sim + (size_t)r1 * NK + c0) =
                make_float2(d[mi][ni][2] * xi1 * cv0, d[mi][ni][3] * xi1 * cv1);
        }
    }
}

// ---------------- per-row: gumbel noise, argmax, softmax, gather ----------------
__global__ __launch_bounds__(256) void rowops_kernel(
    const float* __restrict__ cb,
    float* __restrict__ zq, float* __restrict__ wout, float* __restrict__ idxout,
    uint32_t kh0, uint32_t kh1, uint32_t ks0, uint32_t ks1, uint32_t one) {

    const int b = blockIdx.x;
    const int t = threadIdx.x;
    const int k0 = t << 2;
    const unsigned FULL = 0xffffffffu;
    const int lane = t & 31, warp = t >> 5;

    float4 s4 = *(const float4*)(g_sim + (size_t)b * NK + k0);
    float sim[4] = {s4.x, s4.y, s4.z, s4.w};
    float ts[4];
    float bv = -1.0f; int bk = 0;
#pragma unroll
    for (int j = 0; j < 4; j++) {
        uint32_t flat = (uint32_t)b * (uint32_t)NK + (uint32_t)(k0 + j);
        float uh = uniform_bits(rbits32(kh0, kh1, flat, one));
        float us = uniform_bits(rbits32(ks0, ks1, flat, one));
        float eh = -logf(uh);            // PRECISE: hard-path log
        float es = -__logf(us);          // fast: weights only
        float texp = __expf(sim[j]);
        float h = __fdividef(texp, eh);
        ts[j] = __fdividef(texp, es);
        if (h > bv) { bv = h; bk = k0 + j; }
    }

    __shared__ float sred[8];
    __shared__ int   sredi[8];
    __shared__ int   s_idx;
    __shared__ float s_sum;

#pragma unroll
    for (int o = 16; o; o >>= 1) {
        float ov = __shfl_down_sync(FULL, bv, o);
        int   ok = __shfl_down_sync(FULL, bk, o);
        if (ov > bv || (ov == bv && ok < bk)) { bv = ov; bk = ok; }
    }
    if (lane == 0) { sred[warp] = bv; sredi[warp] = bk; }
    __syncthreads();
    if (t == 0) {
        float v = sred[0]; int k = sredi[0];
#pragma unroll
        for (int w = 1; w < 8; w++)
            if (sred[w] > v || (sred[w] == v && sredi[w] < k)) { v = sred[w]; k = sredi[w]; }
        s_idx = k;
    }

    float ls = (ts[0] + ts[1]) + (ts[2] + ts[3]);
#pragma unroll
    for (int o = 16; o; o >>= 1) ls += __shfl_xor_sync(FULL, ls, o);
    __syncthreads();
    if (lane == 0) sred[warp] = ls;
    __syncthreads();
    if (t == 0) {
        float ss = 0.0f;
#pragma unroll
        for (int w = 0; w < 8; w++) ss += sred[w];
        s_sum = ss;
    }
    __syncthreads();

    float inv = 1.0f / s_sum;
    float4 o4 = make_float4(ts[0] * inv, ts[1] * inv, ts[2] * inv, ts[3] * inv);
    *(float4*)(wout + (size_t)b * NK + k0) = o4;

    int idx = s_idx;
    const float2* crow = (const float2*)(cb + (size_t)idx * ND);
    ((float2*)(zq + (size_t)b * ND))[t] = crow[t];
    if (t == 0) idxout[b] = (float)idx;
}

// ---------------- host-side threefry ----------------
static void tf2x32_host(uint32_t k0, uint32_t k1, uint32_t x0, uint32_t x1,
                        uint32_t* o0, uint32_t* o1) {
    uint32_t k2 = k0 ^ k1 ^ 0x1BD11BDAu;
    x0 += k0; x1 += k1;
#define TF_ROT(r) { x0 += x1; x1 = (x1 << (r)) | (x1 >> (32 - (r))); x1 ^= x0; }
    TF_ROT(13) TF_ROT(15) TF_ROT(26) TF_ROT(6)
    x0 += k1; x1 += k2 + 1u;
    TF_ROT(17) TF_ROT(29) TF_ROT(16) TF_ROT(24)
    x0 += k2; x1 += k0 + 2u;
    TF_ROT(13) TF_ROT(15) TF_ROT(26) TF_ROT(6)
    x0 += k0; x1 += k1 + 3u;
    TF_ROT(17) TF_ROT(29) TF_ROT(16) TF_ROT(24)
    x0 += k1; x1 += k2 + 4u;
    TF_ROT(13) TF_ROT(15) TF_ROT(26) TF_ROT(6)
    x0 += k2; x1 += k0 + 5u;
#undef TF_ROT
    *o0 = x0; *o1 = x1;
}

extern "C" void kernel_launch(void* const* d_in, const int* in_sizes, int n_in,
                              void* d_out, int out_size) {
    const float* state = (const float*)d_in[0];   // (32768, 512)
    const float* cb    = (const float*)d_in[1];   // (1024, 512)

    float* out  = (float*)d_out;
    float* zq   = out;
    float* w    = out + (size_t)NB * ND;
    float* idxp = out + (size_t)NB * ND + (size_t)NB * NK;

    uint32_t kh0, kh1, ks0, ks1;
    tf2x32_host(0u, 42u, 0u, 0u, &kh0, &kh1);
    tf2x32_host(0u, 42u, 0u, 1u, &ks0, &ks1);

    static bool inited = false;
    if (!inited) {
        cudaFuncSetAttribute(gemm_mma_kernel,
                             cudaFuncAttributeMaxDynamicSharedMemorySize, SMEM_GEMM);
        inited = true;
    }

    prep_kernel<<<NB, 128>>>(state, 0);
    prep_kernel<<<NK, 128>>>(cb, 1);

    dim3 ggrid(NK / BN, NB / BM);   // (4, 256); x fastest -> A panel L2 reuse
    gemm_mma_kernel<<<ggrid, 256, SMEM_GEMM>>>();

    rowops_kernel<<<NB, 256>>>(cb, zq, w, idxp, kh0, kh1, ks0, ks1, 1u);
}

// round 17
// speedup vs baseline: 1.1802x; 1.1802x over previous
#include <cuda_runtime.h>
#include <cuda_bf16.h>
#include <stdint.h>

#define NB 32768   // batch rows
#define NK 1024    // codebook entries
#define ND 512     // feature dim
#define KBIG 1536  // 3-term split K: A=[hi|lo|hi], B=[hi|hi|lo]
#define EPSN 1e-8f

// ---------------- device scratch (no allocs allowed) ----------------
__device__ float g_sim[(size_t)NB * NK];   // 128 MB similarity scratch
__device__ float g_xinv[NB];
__device__ float g_cinv[NK];
__device__ __nv_bfloat16 g_ab[(size_t)NB * KBIG];  // 96 MB  [Ahi | Alo | Ahi]
__device__ __nv_bfloat16 g_bb[(size_t)NK * KBIG];  //  3 MB  [Bhi | Bhi | Blo]

// ---------------- PTX helpers (baseline ISA only: sm_80+) ----------------
__device__ __forceinline__ uint32_t smem_u32(const void* p) {
    uint32_t a;
    asm("{ .reg .u64 t; cvta.to.shared.u64 t, %1; cvt.u32.u64 %0, t; }" : "=r"(a) : "l"(p));
    return a;
}
#define CP_ASYNC16(saddr, gptr) \
    asm volatile("cp.async.cg.shared.global [%0], [%1], 16;" :: "r"(saddr), "l"(gptr) : "memory")
#define CP_COMMIT() asm volatile("cp.async.commit_group;" ::: "memory")
#define LDSM_X4(r0, r1, r2, r3, addr) \
    asm volatile("ldmatrix.sync.aligned.m8n8.x4.shared.b16 {%0,%1,%2,%3}, [%4];" \
        : "=r"(r0), "=r"(r1), "=r"(r2), "=r"(r3) : "r"(addr))
#define MMA16816(D, A, B) \
    asm volatile("mma.sync.aligned.m16n8k16.row.col.f32.bf16.bf16.f32 " \
        "{%0,%1,%2,%3}, {%4,%5,%6,%7}, {%8,%9}, {%0,%1,%2,%3};" \
        : "+f"((D)[0]), "+f"((D)[1]), "+f"((D)[2]), "+f"((D)[3]) \
        : "r"((A)[0]), "r"((A)[1]), "r"((A)[2]), "r"((A)[3]), "r"((B)[0]), "r"((B)[1]))

// integer add forced onto the fma pipe: IMAD d = a*one + b (one==1 at runtime)
__device__ __forceinline__ uint32_t addi(uint32_t a, uint32_t one, uint32_t b) {
    uint32_t d;
    asm("mad.lo.u32 %0, %1, %2, %3;" : "=r"(d) : "r"(a), "r"(one), "r"(b));
    return d;
}

// ---------------- threefry2x32, adds on fma pipe (bit-identical) ----------------
__device__ __forceinline__ uint2 tf2x32_imad(uint32_t k0, uint32_t k1,
                                             uint32_t x0, uint32_t x1, uint32_t one) {
    uint32_t k2 = k0 ^ k1 ^ 0x1BD11BDAu;
    x0 = addi(x0, one, k0); x1 = addi(x1, one, k1);
#define TF_ROT(r) { x0 = addi(x0, one, x1); x1 = __funnelshift_l(x1, x1, r); x1 ^= x0; }
    TF_ROT(13) TF_ROT(15) TF_ROT(26) TF_ROT(6)
    x0 = addi(x0, one, k1); x1 = addi(x1, one, k2 + 1u);
    TF_ROT(17) TF_ROT(29) TF_ROT(16) TF_ROT(24)
    x0 = addi(x0, one, k2); x1 = addi(x1, one, k0 + 2u);
    TF_ROT(13) TF_ROT(15) TF_ROT(26) TF_ROT(6)
    x0 = addi(x0, one, k0); x1 = addi(x1, one, k1 + 3u);
    TF_ROT(17) TF_ROT(29) TF_ROT(16) TF_ROT(24)
    x0 = addi(x0, one, k1); x1 = addi(x1, one, k2 + 4u);
    TF_ROT(13) TF_ROT(15) TF_ROT(26) TF_ROT(6)
    x0 = addi(x0, one, k2); x1 = addi(x1, one, k0 + 5u);
#undef TF_ROT
    return make_uint2(x0, x1);
}
__device__ __forceinline__ uint32_t rbits32(uint32_t k0, uint32_t k1,
                                            uint32_t flat, uint32_t one) {
    uint2 r = tf2x32_imad(k0, k1, 0u, flat, one);
    return r.x ^ r.y;
}
__device__ __forceinline__ float uniform_bits(uint32_t bits) {
    float f = __uint_as_float((bits >> 9) | 0x3f800000u) - 1.0f;
    return fmaxf(f + 1e-20f, 1e-20f);
}

// ---------------- fused prep: inv-norm + 3-term bf16 split (one read) ----------------
__global__ __launch_bounds__(128) void prep_kernel(const float* __restrict__ src, int which) {
    const int row = blockIdx.x;
    const int t = threadIdx.x;
    const float4 v = ((const float4*)(src + (size_t)row * ND))[t];

    float s = v.x * v.x + v.y * v.y + v.z * v.z + v.w * v.w;
#pragma unroll
    for (int o = 16; o; o >>= 1) s += __shfl_xor_sync(0xffffffffu, s, o);
    __shared__ float sm[4];
    if ((t & 31) == 0) sm[t >> 5] = s;
    __syncthreads();
    if (t == 0) {
        float tot = sm[0] + sm[1] + sm[2] + sm[3];
        float inv = 1.0f / fmaxf(sqrtf(tot), EPSN);
        if (which == 0) g_xinv[row] = inv; else g_cinv[row] = inv;
    }

    __nv_bfloat16 h0 = __float2bfloat16_rn(v.x), h1 = __float2bfloat16_rn(v.y);
    __nv_bfloat16 h2 = __float2bfloat16_rn(v.z), h3 = __float2bfloat16_rn(v.w);
    __nv_bfloat16 l0 = __float2bfloat16_rn(v.x - __bfloat162float(h0));
    __nv_bfloat16 l1 = __float2bfloat16_rn(v.y - __bfloat162float(h1));
    __nv_bfloat16 l2 = __float2bfloat16_rn(v.z - __bfloat162float(h2));
    __nv_bfloat16 l3 = __float2bfloat16_rn(v.w - __bfloat162float(h3));
    __nv_bfloat162 hA(h0, h1), hB(h2, h3), lA(l0, l1), lB(l2, l3);
    __nv_bfloat16* dst = which ? g_bb : g_ab;
    __nv_bfloat16* base = dst + (size_t)row * KBIG + t * 4;
    __nv_bfloat162* s0 = (__nv_bfloat162*)(base);
    __nv_bfloat162* s1 = (__nv_bfloat162*)(base + ND);
    __nv_bfloat162* s2 = (__nv_bfloat162*)(base + 2 * ND);
    s0[0] = hA; s0[1] = hB;
    if (which == 0) { s1[0] = lA; s1[1] = lB; s2[0] = hA; s2[1] = hB; }
    else            { s1[0] = hA; s1[1] = hB; s2[0] = lA; s2[1] = lB; }
}

// ------- bf16 mma.sync GEMM: 128-thr block, tile 128x128, warp tile 64x64, 3-stage -------
#define BM 128
#define BN 128
#define BK 32
#define SSTR 40                           // smem row stride in bf16 (32 + 8 pad)
#define SA_BYTES (BM * SSTR * 2)          // 10240
#define SB_BYTES (BN * SSTR * 2)          // 10240
#define STAGE_TOT (SA_BYTES + SB_BYTES)   // 20480
#define SMEM_GEMM (3 * STAGE_TOT)         // 61440
#define NKT (KBIG / BK)                   // 48

__global__ void __maxnreg__(232) gemm_mma_kernel() {
    extern __shared__ __align__(16) char dynsm[];
    const int tid = threadIdx.x;            // 128 threads, 4 warps
    const int wid = tid >> 5, l = tid & 31;
    const int wm = wid >> 1, wn = wid & 1;  // warp grid 2(m) x 2(n), tile 64x64
    const int bm = blockIdx.y * BM, bn = blockIdx.x * BN;

    uint32_t sA[3], sB[3];
#pragma unroll
    for (int s = 0; s < 3; s++) {
        sA[s] = smem_u32(dynsm + s * STAGE_TOT);
        sB[s] = smem_u32(dynsm + s * STAGE_TOT + SA_BYTES);
    }

    float d[4][8][4];
#pragma unroll
    for (int mi = 0; mi < 4; mi++)
#pragma unroll
        for (int ni = 0; ni < 8; ni++)
#pragma unroll
            for (int r = 0; r < 4; r++) d[mi][ni][r] = 0.0f;

    // per tile: A = 512 segs of 16B, B = 512 segs; 128 threads -> 4 each
#define LOAD_TILE(kt, buf) do { \
    int _k0 = (kt) * BK; \
    _Pragma("unroll") \
    for (int _q = 0; _q < 4; _q++) { \
      int _s = tid + _q * 128; int _r = _s >> 2, _c = _s & 3; \
      CP_ASYNC16(sA[buf] + _r * (SSTR * 2) + _c * 16, \
                 g_ab + (size_t)(bm + _r) * KBIG + _k0 + _c * 8); } \
    _Pragma("unroll") \
    for (int _q = 0; _q < 4; _q++) { \
      int _s = tid + _q * 128; int _r = _s >> 2, _c = _s & 3; \
      CP_ASYNC16(sB[buf] + _r * (SSTR * 2) + _c * 16, \
                 g_bb + (size_t)(bn + _r) * KBIG + _k0 + _c * 8); } \
    CP_COMMIT(); \
} while (0)

    LOAD_TILE(0, 0);
    LOAD_TILE(1, 1);

    int buf = 0, nbuf = 2;
    for (int kt = 0; kt < NKT; kt++) {
        asm volatile("cp.async.wait_group 1;" ::: "memory");
        __syncthreads();
        if (kt + 2 < NKT) LOAD_TILE(kt + 2, nbuf);

#pragma unroll
        for (int ks = 0; ks < 2; ks++) {
            uint32_t a[4][4];
#pragma unroll
            for (int mi = 0; mi < 4; mi++) {
                int row = wm * 64 + mi * 16 + (l & 15);
                int col = ks * 16 + (l >> 4) * 8;
                LDSM_X4(a[mi][0], a[mi][1], a[mi][2], a[mi][3],
                        sA[buf] + row * (SSTR * 2) + col * 2);
            }
            uint32_t b[8][2];
#pragma unroll
            for (int p = 0; p < 4; p++) {
                int row = wn * 64 + p * 16 + (l & 7) + ((l >> 4) & 1) * 8;
                int col = ks * 16 + ((l >> 3) & 1) * 8;
                LDSM_X4(b[p * 2][0], b[p * 2][1], b[p * 2 + 1][0], b[p * 2 + 1][1],
                        sB[buf] + row * (SSTR * 2) + col * 2);
            }
#pragma unroll
            for (int mi = 0; mi < 4; mi++)
#pragma unroll
                for (int ni = 0; ni < 8; ni++)
                    MMA16816(d[mi][ni], a[mi], b[ni]);
        }
        buf = (buf == 2) ? 0 : buf + 1;
        nbuf = (nbuf == 2) ? 0 : nbuf + 1;
    }

    // epilogue: scale by inv norms, write fp32 sim
#pragma unroll
    for (int mi = 0; mi < 4; mi++) {
        int r0 = bm + wm * 64 + mi * 16 + (l >> 2);
        int r1 = r0 + 8;
        float xi0 = g_xinv[r0], xi1 = g_xinv[r1];
#pragma unroll
        for (int ni = 0; ni < 8; ni++) {
            int c0 = bn + wn * 64 + ni * 8 + ((l & 3) << 1);
            float cv0 = g_cinv[c0], cv1 = g_cinv[c0 + 1];
            *(float2*)(g_sim + (size_t)r0 * NK + c0) =
                make_float2(d[mi][ni][0] * xi0 * cv0, d[mi][ni][1] * xi0 * cv1);
            *(float2*)(g_sim + (size_t)r1 * NK + c0) =
                make_float2(d[mi][ni][2] * xi1 * cv0, d[mi][ni][3] * xi1 * cv1);
        }
    }
}

// ---------------- per-row: gumbel noise, argmax, softmax, gather ----------------
__global__ __launch_bounds__(256) void rowops_kernel(
    const float* __restrict__ cb,
    float* __restrict__ zq, float* __restrict__ wout, float* __restrict__ idxout,
    uint32_t kh0, uint32_t kh1, uint32_t ks0, uint32_t ks1, uint32_t one) {

    const int b = blockIdx.x;
    const int t = threadIdx.x;
    const int k0 = t << 2;
    const unsigned FULL = 0xffffffffu;
    const int lane = t & 31, warp = t >> 5;

    float4 s4 = *(const float4*)(g_sim + (size_t)b * NK + k0);
    float sim[4] = {s4.x, s4.y, s4.z, s4.w};
    float ts[4];
    float bv = -1.0f; int bk = 0;
#pragma unroll
    for (int j = 0; j < 4; j++) {
        uint32_t flat = (uint32_t)b * (uint32_t)NK + (uint32_t)(k0 + j);
        float uh = uniform_bits(rbits32(kh0, kh1, flat, one));
        float us = uniform_bits(rbits32(ks0, ks1, flat, one));
        float eh = -logf(uh);            // PRECISE: hard-path log
        float es = -__logf(us);          // fast: weights only
        float texp = __expf(sim[j]);
        float h = __fdividef(texp, eh);
        ts[j] = __fdividef(texp, es);
        if (h > bv) { bv = h; bk = k0 + j; }
    }

    __shared__ float sred[8];
    __shared__ int   sredi[8];
    __shared__ int   s_idx;
    __shared__ float s_sum;

#pragma unroll
    for (int o = 16; o; o >>= 1) {
        float ov = __shfl_down_sync(FULL, bv, o);
        int   ok = __shfl_down_sync(FULL, bk, o);
        if (ov > bv || (ov == bv && ok < bk)) { bv = ov; bk = ok; }
    }
    if (lane == 0) { sred[warp] = bv; sredi[warp] = bk; }
    __syncthreads();
    if (t == 0) {
        float v = sred[0]; int k = sredi[0];
#pragma unroll
        for (int w = 1; w < 8; w++)
            if (sred[w] > v || (sred[w] == v && sredi[w] < k)) { v = sred[w]; k = sredi[w]; }
        s_idx = k;
    }

    float ls = (ts[0] + ts[1]) + (ts[2] + ts[3]);
#pragma unroll
    for (int o = 16; o; o >>= 1) ls += __shfl_xor_sync(FULL, ls, o);
    __syncthreads();
    if (lane == 0) sred[warp] = ls;
    __syncthreads();
    if (t == 0) {
        float ss = 0.0f;
#pragma unroll
        for (int w = 0; w < 8; w++) ss += sred[w];
        s_sum = ss;
    }
    __syncthreads();

    float inv = 1.0f / s_sum;
    float4 o4 = make_float4(ts[0] * inv, ts[1] * inv, ts[2] * inv, ts[3] * inv);
    *(float4*)(wout + (size_t)b * NK + k0) = o4;

    int idx = s_idx;
    const float2* crow = (const float2*)(cb + (size_t)idx * ND);
    ((float2*)(zq + (size_t)b * ND))[t] = crow[t];
    if (t == 0) idxout[b] = (float)idx;
}

// ---------------- host-side threefry ----------------
static void tf2x32_host(uint32_t k0, uint32_t k1, uint32_t x0, uint32_t x1,
                        uint32_t* o0, uint32_t* o1) {
    uint32_t k2 = k0 ^ k1 ^ 0x1BD11BDAu;
    x0 += k0; x1 += k1;
#define TF_ROT(r) { x0 += x1; x1 = (x1 << (r)) | (x1 >> (32 - (r))); x1 ^= x0; }
    TF_ROT(13) TF_ROT(15) TF_ROT(26) TF_ROT(6)
    x0 += k1; x1 += k2 + 1u;
    TF_ROT(17) TF_ROT(29) TF_ROT(16) TF_ROT(24)
    x0 += k2; x1 += k0 + 2u;
    TF_ROT(13) TF_ROT(15) TF_ROT(26) TF_ROT(6)
    x0 += k0; x1 += k1 + 3u;
    TF_ROT(17) TF_ROT(29) TF_ROT(16) TF_ROT(24)
    x0 += k1; x1 += k2 + 4u;
    TF_ROT(13) TF_ROT(15) TF_ROT(26) TF_ROT(6)
    x0 += k2; x1 += k0 + 5u;
#undef TF_ROT
    *o0 = x0; *o1 = x1;
}

extern "C" void kernel_launch(void* const* d_in, const int* in_sizes, int n_in,
                              void* d_out, int out_size) {
    const float* state = (const float*)d_in[0];   // (32768, 512)
    const float* cb    = (const float*)d_in[1];   // (1024, 512)

    float* out  = (float*)d_out;
    float* zq   = out;
    float* w    = out + (size_t)NB * ND;
    float* idxp = out + (size_t)NB * ND + (size_t)NB * NK;

    uint32_t kh0, kh1, ks0, ks1;
    tf2x32_host(0u, 42u, 0u, 0u, &kh0, &kh1);
    tf2x32_host(0u, 42u, 0u, 1u, &ks0, &ks1);

    static bool inited = false;
    if (!inited) {
        cudaFuncSetAttribute(gemm_mma_kernel,
                             cudaFuncAttributeMaxDynamicSharedMemorySize, SMEM_GEMM);
        inited = true;
    }

    prep_kernel<<<NB, 128>>>(state, 0);
    prep_kernel<<<NK, 128>>>(cb, 1);

    dim3 ggrid(NK / BN, NB / BM);   // (8, 256); x fastest -> A panel L2 reuse
    gemm_mma_kernel<<<ggrid, 128, SMEM_GEMM>>>();

    rowops_kernel<<<NB, 256>>>(cb, zq, w, idxp, kh0, kh1, ks0, ks1, 1u);
}